// round 17
// baseline (speedup 1.0000x reference)
#include <cuda_runtime.h>
#include <cuda_bf16.h>

#define T_ 128
#define B_ 512
#define D_ 500
#define D4_ 125   // D/4 float4 per row
#define PF 8      // prefetch depth (rows ahead)
#define CPB 32    // columns per setup block

// Scratch (no allocation allowed): control-plane metadata.
// g_meta[b*T_+t]: bit0 = token t valid; bits[1:15] = (seg_to_emit_after_t + 1), 0 = none.
__device__ unsigned short g_meta[B_ * T_];
__device__ int g_newlen[B_];

// ---------------------------------------------------------------------------
// Kernel 1: SIMD-lockstep greedy packing scans.
// 16 blocks x 128 threads, 32 columns per block.
//  - Gather: warp w, lane l reads src[(4r+w)*B + c0+l] -> 32 consecutive ints
//    per warp access (fully coalesced), all 32 loads register-batched (MLP).
//  - Lengths stored as uint at s_len[t*32 + lane]: conflict-free banks.
//  - Warp 0's 32 lanes run 32 branchless scans IN LOCKSTEP: the 128-step
//    serial recurrence is paid once per 32 columns instead of per column.
//    Emit-stores write ((seg+1)<<1)|1 (last_t is always valid) -> no smem RMW.
//  - Writeback: 4 threads per column, 64B contiguous ushort runs.
// ---------------------------------------------------------------------------
__global__ __launch_bounds__(128) void setup_kernel(const int* __restrict__ src,
                                                    const int* __restrict__ token_lengths,
                                                    const int* __restrict__ token_len_p)
{
    __shared__ unsigned int s_len [T_ * CPB];   // 16KB  [t*32 + col]
    __shared__ unsigned int s_meta[T_ * CPB];   // 16KB  [t*32 + col]

    int tid  = threadIdx.x;
    int lane = tid & 31;
    int w    = tid >> 5;                // 0..3
    int c0   = blockIdx.x * CPB;

    // ---- coalesced gather, fully register-batched ----
    int sv[T_ / 4];                     // tokens t = 4r + w
    #pragma unroll
    for (int r = 0; r < T_ / 4; r++)
        sv[r] = __ldcg(&src[(4 * r + w) * B_ + c0 + lane]);

    // zero meta while the src loads are in flight
    #pragma unroll
    for (int k = tid; k < T_ * CPB; k += 128) s_meta[k] = 0u;

    #pragma unroll
    for (int r = 0; r < T_ / 4; r++) {
        int s = sv[r];
        int l = (s == 1) ? 0 : ((s == 0) ? 4 : token_lengths[s]);
        s_len[(4 * r + w) * CPB + lane] = (unsigned int)l;
    }
    __syncthreads();

    // ---- 32 lockstep scans (warp 0), branchless, conflict-free LDS ----
    if (w == 0) {
        int token_len = token_len_p ? token_len_p[0] : 20;

        int seg = 0, curr = 0, last_t = 0;
        #pragma unroll 8
        for (int t = 0; t < T_; t++) {
            int ll = (int)s_len[t * CPB + lane];
            bool valid = (ll != 0);
            bool close = valid & (curr > 0) & (curr + ll > token_len);
            if (close) s_meta[last_t * CPB + lane] = (unsigned int)(((seg + 1) << 1) | 1);
            seg  += (int)close;
            curr  = close ? 0 : curr;
            if (valid) s_meta[t * CPB + lane] = 1u;
            curr  += valid ? ll : 0;
            last_t = valid ? t : last_t;
        }
        bool trail = (curr > 0);
        if (trail) s_meta[last_t * CPB + lane] = (unsigned int)(((seg + 1) << 1) | 1);
        seg += (int)trail;
        g_newlen[c0 + lane] = seg;
    }
    __syncthreads();

    // ---- writeback: 4 threads per column, 32 t's each (64B runs) ----
    {
        int cl = tid >> 2;              // 0..31
        int t0 = (tid & 3) * 32;
        #pragma unroll 8
        for (int t = t0; t < t0 + 32; t++)
            g_meta[(c0 + cl) * T_ + t] = (unsigned short)s_meta[t * CPB + cl];
    }
}

// ---------------------------------------------------------------------------
// Kernel 2 (data plane + rank): one block per SOURCE column b, 128 threads.
// EXACT R12 body (proven 37.1us, DRAM 70.8%). Reads each input row ONCE:
// accumulate valid rows, write-through rows t>=L, flush the accumulator into
// out[seg] at segment-end flags. Traffic: 262 MB total.
// ---------------------------------------------------------------------------
__global__ __launch_bounds__(T_) void merge_kernel(const float4* __restrict__ embv,
                                                   float4* __restrict__ outv,
                                                   float* __restrict__ out_len,
                                                   int write_len)
{
    __shared__ unsigned short s_meta[T_];
    __shared__ int s_warp[4];
    __shared__ int s_rank;

    int b = blockIdx.x;
    int i = threadIdx.x;

    const long stride = (long)B_ * D4_;        // float4s per t-slab
    bool active = (i < D4_);
    int  ic     = active ? i : (D4_ - 1);      // clamped: loads always valid
    long ibase  = (long)b * D4_ + ic;

    // ---- kick off prefetch pipeline first (deep MLP) ----
    float4 buf[PF];
    #pragma unroll
    for (int k = 0; k < PF; k++) buf[k] = embv[ibase + (long)k * stride];

    // ---- overlap: meta load + rank reduction while loads are in flight ----
    s_meta[i] = g_meta[b * T_ + i];

    int myl = g_newlen[b];
    const int4* len4 = (const int4*)g_newlen;  // 512 / 4 = 128 == blockDim
    int4 v4 = len4[i];
    int j = 4 * i;
    int cnt = 0;
    cnt += (v4.x > myl) || (v4.x == myl && (j + 0) < b);
    cnt += (v4.y > myl) || (v4.y == myl && (j + 1) < b);
    cnt += (v4.z > myl) || (v4.z == myl && (j + 2) < b);
    cnt += (v4.w > myl) || (v4.w == myl && (j + 3) < b);
    #pragma unroll
    for (int o = 16; o > 0; o >>= 1) cnt += __shfl_down_sync(0xFFFFFFFFu, cnt, o);
    if ((i & 31) == 0) s_warp[i >> 5] = cnt;
    __syncthreads();
    if (i == 0) {
        int rank = s_warp[0] + s_warp[1] + s_warp[2] + s_warp[3];
        s_rank = rank;
        if (write_len) out_len[rank] = (float)myl;
    }
    __syncthreads();

    int  bo    = s_rank;
    int  L     = myl;
    long obase = (long)bo * D4_ + i;

    // ---- streaming loop with 8-deep ring buffer ----
    float4 acc = make_float4(0.f, 0.f, 0.f, 0.f);

    for (int to = 0; to < T_; to += PF) {
        #pragma unroll
        for (int k = 0; k < PF; k++) {
            int t = to + k;
            float4 v = buf[k];
            if (t + PF < T_)                       // refill slot (stays PF ahead)
                buf[k] = embv[ibase + (long)(t + PF) * stride];

            unsigned int m = s_meta[t];
            if (m & 1u) {
                acc.x += v.x; acc.y += v.y; acc.z += v.z; acc.w += v.w;
            }
            if (t >= L && active)
                outv[obase + (long)t * stride] = v;

            unsigned int e = m >> 1;
            if (e && active) {
                outv[obase + (long)((int)e - 1) * stride] = acc;
                acc = make_float4(0.f, 0.f, 0.f, 0.f);
            }
        }
    }
}

// ---------------------------------------------------------------------------
extern "C" void kernel_launch(void* const* d_in, const int* in_sizes, int n_in,
                              void* d_out, int out_size)
{
    const float* emb           = (const float*)d_in[0];   // (T,B,D) fp32
    const int*   src           = (const int*)d_in[1];     // (T,B) int32
    // d_in[2] = lengths (unused by reference computation)
    const int*   token_lengths = (const int*)d_in[3];     // (VOCAB,) int32
    const int*   token_len_p   = (n_in >= 5) ? (const int*)d_in[4] : nullptr;

    float* out = (float*)d_out;
    const long emb_elems = (long)T_ * B_ * D_;
    int write_len = (out_size >= emb_elems + B_) ? 1 : 0;

    setup_kernel<<<B_ / CPB, 128>>>(src, token_lengths, token_len_p);
    merge_kernel<<<B_, T_>>>((const float4*)emb, (float4*)out,
                             out + emb_elems, write_len);
}